// round 1
// baseline (speedup 1.0000x reference)
#include <cuda_runtime.h>
#include <cstdint>

#define NUM_USERS 100000
#define NUM_ITEMS 50000
#define DIM 64

// Scratch: __device__ globals (allocation-free rule)
__device__ float g_ubuf0[NUM_USERS * DIM];
__device__ float g_ubuf1[NUM_USERS * DIM];
__device__ float g_usum [NUM_USERS * DIM];
__device__ float g_ssum [NUM_USERS * DIM];
__device__ float g_ibuf0[NUM_ITEMS * DIM];
__device__ float g_ibuf1[NUM_ITEMS * DIM];
__device__ float g_isum [NUM_ITEMS * DIM];

__device__ __forceinline__ void red_add_v4(float* p, float4 v) {
    asm volatile("red.global.add.v4.f32 [%0], {%1, %2, %3, %4};"
                 :: "l"(p), "f"(v.x), "f"(v.y), "f"(v.z), "f"(v.w) : "memory");
}

// Fused bipartite pass: u_dst[r] += v*i_src[c]  AND  i_dst[c] += v*u_src[r]
// 16 lanes per edge, float4 per lane.
__global__ void spmm_r_fused(const int* __restrict__ rows, const int* __restrict__ cols,
                             const float* __restrict__ vals,
                             const float* __restrict__ u_src, const float* __restrict__ i_src,
                             float* __restrict__ u_dst, float* __restrict__ i_dst,
                             int nnz) {
    int gid   = blockIdx.x * blockDim.x + threadIdx.x;
    int e     = gid >> 4;
    int lane  = gid & 15;
    int estr  = (gridDim.x * blockDim.x) >> 4;
    for (; e < nnz; e += estr) {
        int r = 0, c = 0; float v = 0.f;
        if (lane == 0) { r = rows[e]; c = cols[e]; v = vals[e]; }
        r = __shfl_sync(0xffffffffu, r, 0, 16);
        c = __shfl_sync(0xffffffffu, c, 0, 16);
        v = __shfl_sync(0xffffffffu, v, 0, 16);

        const float4 iv = __ldg((const float4*)(i_src) + c * 16 + lane);
        const float4 uv = __ldg((const float4*)(u_src) + r * 16 + lane);

        float4 a = make_float4(v * iv.x, v * iv.y, v * iv.z, v * iv.w);
        float4 b = make_float4(v * uv.x, v * uv.y, v * uv.z, v * uv.w);
        red_add_v4(u_dst + r * DIM + lane * 4, a);
        red_add_v4(i_dst + c * DIM + lane * 4, b);
    }
}

// Social pass: dst[r] += v * src[c]   (users x users)
__global__ void spmm_s(const int* __restrict__ rows, const int* __restrict__ cols,
                       const float* __restrict__ vals,
                       const float* __restrict__ src, float* __restrict__ dst,
                       int nnz) {
    int gid  = blockIdx.x * blockDim.x + threadIdx.x;
    int e    = gid >> 4;
    int lane = gid & 15;
    int estr = (gridDim.x * blockDim.x) >> 4;
    for (; e < nnz; e += estr) {
        int r = 0, c = 0; float v = 0.f;
        if (lane == 0) { r = rows[e]; c = cols[e]; v = vals[e]; }
        r = __shfl_sync(0xffffffffu, r, 0, 16);
        c = __shfl_sync(0xffffffffu, c, 0, 16);
        v = __shfl_sync(0xffffffffu, v, 0, 16);

        const float4 sv = __ldg((const float4*)(src) + c * 16 + lane);
        red_add_v4(dst + r * DIM + lane * 4,
                   make_float4(v * sv.x, v * sv.y, v * sv.z, v * sv.w));
    }
}

// sum[i] += src[i]  (float4)
__global__ void add_inplace(float* __restrict__ sum, const float* __restrict__ src, int n4) {
    int i = blockIdx.x * blockDim.x + threadIdx.x;
    int s = gridDim.x * blockDim.x;
    float4* S = (float4*)sum;
    const float4* A = (const float4*)src;
    for (; i < n4; i += s) {
        float4 x = S[i], y = A[i];
        x.x += y.x; x.y += y.y; x.z += y.z; x.w += y.w;
        S[i] = x;
    }
}

// Final combine + L2 normalize. Rows 0..NUM_USERS-1 = user, then items.
__global__ void finalize_kernel(const float* __restrict__ usum, const float* __restrict__ ssum,
                                const float* __restrict__ isum, float* __restrict__ out) {
    int gid  = blockIdx.x * blockDim.x + threadIdx.x;
    int row  = gid >> 4;
    int lane = gid & 15;
    if (row >= NUM_USERS + NUM_ITEMS) return;

    float4 f;
    if (row < NUM_USERS) {
        float4 a = __ldg((const float4*)usum + row * 16 + lane);
        float4 b = __ldg((const float4*)ssum + row * 16 + lane);
        const float ca = 0.6f / 4.0f;      // 0.15
        const float cb = 0.4f / 3.0f;
        f = make_float4(ca * a.x + cb * b.x, ca * a.y + cb * b.y,
                        ca * a.z + cb * b.z, ca * a.w + cb * b.w);
    } else {
        int ir = row - NUM_USERS;
        float4 a = __ldg((const float4*)isum + ir * 16 + lane);
        const float ci = 1.0f / 4.0f;
        f = make_float4(ci * a.x, ci * a.y, ci * a.z, ci * a.w);
    }
    float ss = f.x * f.x + f.y * f.y + f.z * f.z + f.w * f.w;
    #pragma unroll
    for (int o = 8; o > 0; o >>= 1)
        ss += __shfl_xor_sync(0xffffffffu, ss, o, 16);
    float inv = 1.0f / fmaxf(sqrtf(ss), 1e-12f);
    f.x *= inv; f.y *= inv; f.z *= inv; f.w *= inv;
    ((float4*)out)[row * 16 + lane] = f;
}

extern "C" void kernel_launch(void* const* d_in, const int* in_sizes, int n_in,
                              void* d_out, int out_size) {
    const float* user_emb = (const float*)d_in[0];
    const float* item_emb = (const float*)d_in[1];
    const float* r_vals   = (const float*)d_in[2];
    const float* s_vals   = (const float*)d_in[3];
    const int*   r_rows   = (const int*)d_in[4];
    const int*   r_cols   = (const int*)d_in[5];
    const int*   s_rows   = (const int*)d_in[6];
    const int*   s_cols   = (const int*)d_in[7];
    const int nnz_r = in_sizes[2];
    const int nnz_s = in_sizes[3];
    float* out = (float*)d_out;

    float *u0, *u1, *usum, *ssum, *i0, *i1, *isum;
    cudaGetSymbolAddress((void**)&u0,   g_ubuf0);
    cudaGetSymbolAddress((void**)&u1,   g_ubuf1);
    cudaGetSymbolAddress((void**)&usum, g_usum);
    cudaGetSymbolAddress((void**)&ssum, g_ssum);
    cudaGetSymbolAddress((void**)&i0,   g_ibuf0);
    cudaGetSymbolAddress((void**)&i1,   g_ibuf1);
    cudaGetSymbolAddress((void**)&isum, g_isum);

    const size_t ub = (size_t)NUM_USERS * DIM * sizeof(float);
    const size_t ib = (size_t)NUM_ITEMS * DIM * sizeof(float);
    const int un4 = NUM_USERS * DIM / 4;
    const int in4 = NUM_ITEMS * DIM / 4;

    const int TB = 256;
    const int gr = (int)(((long long)nnz_r * 16 + TB - 1) / TB);
    const int gs = (int)(((long long)nnz_s * 16 + TB - 1) / TB);
    const int ga_u = (un4 + TB - 1) / TB;
    const int ga_i = (in4 + TB - 1) / TB;
    const int gf = ((NUM_USERS + NUM_ITEMS) * 16 + TB - 1) / TB;

    // init sums
    cudaMemcpyAsync(usum, user_emb, ub, cudaMemcpyDeviceToDevice);
    cudaMemcpyAsync(isum, item_emb, ib, cudaMemcpyDeviceToDevice);
    cudaMemcpyAsync(ssum, user_emb, ub, cudaMemcpyDeviceToDevice);

    // ----- bipartite layer 1 -----
    cudaMemsetAsync(u0, 0, ub);
    cudaMemsetAsync(i0, 0, ib);
    spmm_r_fused<<<gr, TB>>>(r_rows, r_cols, r_vals, user_emb, item_emb, u0, i0, nnz_r);
    add_inplace<<<ga_u, TB>>>(usum, u0, un4);
    add_inplace<<<ga_i, TB>>>(isum, i0, in4);

    // ----- layer 2 -----
    cudaMemsetAsync(u1, 0, ub);
    cudaMemsetAsync(i1, 0, ib);
    spmm_r_fused<<<gr, TB>>>(r_rows, r_cols, r_vals, u0, i0, u1, i1, nnz_r);
    add_inplace<<<ga_u, TB>>>(usum, u1, un4);
    add_inplace<<<ga_i, TB>>>(isum, i1, in4);

    // ----- layer 3 -----
    cudaMemsetAsync(u0, 0, ub);
    cudaMemsetAsync(i0, 0, ib);
    spmm_r_fused<<<gr, TB>>>(r_rows, r_cols, r_vals, u1, i1, u0, i0, nnz_r);
    add_inplace<<<ga_u, TB>>>(usum, u0, un4);
    add_inplace<<<ga_i, TB>>>(isum, i0, in4);

    // ----- social layer 1 (reuse u-buffers; dead after bipartite) -----
    cudaMemsetAsync(u1, 0, ub);
    spmm_s<<<gs, TB>>>(s_rows, s_cols, s_vals, user_emb, u1, nnz_s);
    add_inplace<<<ga_u, TB>>>(ssum, u1, un4);

    // ----- social layer 2 -----
    cudaMemsetAsync(u0, 0, ub);
    spmm_s<<<gs, TB>>>(s_rows, s_cols, s_vals, u1, u0, nnz_s);
    add_inplace<<<ga_u, TB>>>(ssum, u0, un4);

    // ----- finalize: combine + l2-normalize -----
    finalize_kernel<<<gf, TB>>>(usum, ssum, isum, out);
}